// round 7
// baseline (speedup 1.0000x reference)
#include <cuda_runtime.h>
#include <math.h>

#define N_NODES 100000
#define N_IN    512
#define N_HID   256
#define N_OUT   64
#define HOP     10
#define MAX_E   1600000

// ---------------- scratch (device globals; no allocation allowed) ----------
__device__ float g_h1[(size_t)N_NODES * N_HID];                 // 102.4 MB
__device__ float g_H[(size_t)(HOP + 1) * N_NODES * N_OUT];      // 281.6 MB
__device__ int   g_row[MAX_E];
__device__ int   g_col[MAX_E];
__device__ int   g_is32;

// ---------------- index dtype detection ------------------------------------
// If the edge index arrays are int64 (little-endian), the int32 view has all
// high words == 0 (values < 2^31). If they are int32, odd positions are just
// ordinary indices (mostly nonzero). Scan 2048 odd positions of edge_row.
__global__ void detect_idx_kernel(const int* __restrict__ p) {
    __shared__ int any;
    if (threadIdx.x == 0) any = 0;
    __syncthreads();
    for (int i = threadIdx.x; i < 2048; i += blockDim.x) {
        if (p[2 * i + 1] != 0) any = 1;  // racy OR-write, fine
    }
    __syncthreads();
    if (threadIdx.x == 0) g_is32 = any;
}

__global__ void convert_idx_kernel(const void* __restrict__ rp,
                                   const void* __restrict__ cp, int E) {
    int e = blockIdx.x * blockDim.x + threadIdx.x;
    if (e >= E) return;
    if (g_is32) {
        g_row[e] = ((const int*)rp)[e];
        g_col[e] = ((const int*)cp)[e];
    } else {
        g_row[e] = (int)((const long long*)rp)[e];
        g_col[e] = (int)((const long long*)cp)[e];
    }
}

// ---------------- tiled NT GEMM: C[m,n] = act(sum_k A[m,k]*B[n,k] + bias[n])
// A: [M,K] row-major, B: [Ncols,K] row-major. BM=BN=64, BK=16, 256 thr, 4x4/thr.
template <bool RELU>
__global__ __launch_bounds__(256) void gemm_nt_kernel(
    const float* __restrict__ A, const float* __restrict__ B,
    const float* __restrict__ bias, float* __restrict__ C,
    int M, int Ncols, int K) {
    const int BM = 64, BN = 64, BK = 16;
    __shared__ float As[BK][BM];
    __shared__ float Bs[BK][BN];

    int tid = threadIdx.x;
    int tx = tid & 15;       // 0..15 -> n sub-tile
    int ty = tid >> 4;       // 0..15 -> m sub-tile
    int row0 = blockIdx.x * BM;
    int col0 = blockIdx.y * BN;

    float acc[4][4];
#pragma unroll
    for (int i = 0; i < 4; i++)
#pragma unroll
        for (int j = 0; j < 4; j++) acc[i][j] = 0.f;

    int lr = tid >> 2;       // 0..63 : row within tile for loads
    int kg = tid & 3;        // 0..3  : float4 group along K

    for (int k0 = 0; k0 < K; k0 += BK) {
        float4 av = make_float4(0.f, 0.f, 0.f, 0.f);
        if (row0 + lr < M)
            av = *(const float4*)(A + (long long)(row0 + lr) * K + k0 + kg * 4);
        As[kg * 4 + 0][lr] = av.x;
        As[kg * 4 + 1][lr] = av.y;
        As[kg * 4 + 2][lr] = av.z;
        As[kg * 4 + 3][lr] = av.w;

        float4 bv = make_float4(0.f, 0.f, 0.f, 0.f);
        if (col0 + lr < Ncols)
            bv = *(const float4*)(B + (long long)(col0 + lr) * K + k0 + kg * 4);
        Bs[kg * 4 + 0][lr] = bv.x;
        Bs[kg * 4 + 1][lr] = bv.y;
        Bs[kg * 4 + 2][lr] = bv.z;
        Bs[kg * 4 + 3][lr] = bv.w;

        __syncthreads();
#pragma unroll
        for (int kk = 0; kk < BK; kk++) {
            float4 a = *(const float4*)&As[kk][ty * 4];
            float4 b = *(const float4*)&Bs[kk][tx * 4];
            acc[0][0] = fmaf(a.x, b.x, acc[0][0]);
            acc[0][1] = fmaf(a.x, b.y, acc[0][1]);
            acc[0][2] = fmaf(a.x, b.z, acc[0][2]);
            acc[0][3] = fmaf(a.x, b.w, acc[0][3]);
            acc[1][0] = fmaf(a.y, b.x, acc[1][0]);
            acc[1][1] = fmaf(a.y, b.y, acc[1][1]);
            acc[1][2] = fmaf(a.y, b.z, acc[1][2]);
            acc[1][3] = fmaf(a.y, b.w, acc[1][3]);
            acc[2][0] = fmaf(a.z, b.x, acc[2][0]);
            acc[2][1] = fmaf(a.z, b.y, acc[2][1]);
            acc[2][2] = fmaf(a.z, b.z, acc[2][2]);
            acc[2][3] = fmaf(a.z, b.w, acc[2][3]);
            acc[3][0] = fmaf(a.w, b.x, acc[3][0]);
            acc[3][1] = fmaf(a.w, b.y, acc[3][1]);
            acc[3][2] = fmaf(a.w, b.z, acc[3][2]);
            acc[3][3] = fmaf(a.w, b.w, acc[3][3]);
        }
        __syncthreads();
    }

#pragma unroll
    for (int i = 0; i < 4; i++) {
        int m = row0 + ty * 4 + i;
        if (m >= M) continue;
#pragma unroll
        for (int j = 0; j < 4; j++) {
            int n = col0 + tx * 4 + j;
            if (n >= Ncols) continue;
            float v = acc[i][j] + bias[n];
            if (RELU) v = fmaxf(v, 0.f);
            C[(long long)m * Ncols + n] = v;
        }
    }
}

// ---------------- zero hop buffers -----------------------------------------
__global__ void zero_kernel(float* __restrict__ p, int n4) {
    int i = blockIdx.x * blockDim.x + threadIdx.x;
    if (i < n4) ((float4*)p)[i] = make_float4(0.f, 0.f, 0.f, 0.f);
}

// ---------------- COO SpMM (edge-parallel, vector-RED scatter) -------------
// h_{k+1}[r] += val * h_k[c]. 16 threads per edge, float4 per thread.
// Scatter uses one red.global.add.v4.f32 (sm_90+) instead of 4 scalar REDs.
__global__ void spmm_kernel(const float* __restrict__ vals, int hop, int E) {
    int g = blockIdx.x * blockDim.x + threadIdx.x;
    int e = g >> 4;
    int l = g & 15;
    if (e >= E) return;
    int r = g_row[e];
    int c = g_col[e];
    float v = vals[e];
    const float* hin = g_H + (size_t)hop * N_NODES * N_OUT;
    float* hout = g_H + (size_t)(hop + 1) * N_NODES * N_OUT;
    float4 h = *(const float4*)(hin + (size_t)c * N_OUT + l * 4);
    float* o = hout + (size_t)r * N_OUT + l * 4;
    asm volatile("red.global.add.v4.f32 [%0], {%1, %2, %3, %4};"
                 :: "l"(o), "f"(v * h.x), "f"(v * h.y),
                    "f"(v * h.z), "f"(v * h.w)
                 : "memory");
}

// ---------------- hop attention --------------------------------------------
// logit_nk = dot(H[k][n][:], s[:64]); S = sigmoid(logit); out[n] = sum_k S_k * H[k][n]
__global__ void attn_kernel(const float* __restrict__ s,
                            float* __restrict__ out, int N) {
    int g = blockIdx.x * blockDim.x + threadIdx.x;
    int n = g >> 5;
    int lane = g & 31;
    if (n >= N) return;
    float s0 = s[lane * 2 + 0];
    float s1 = s[lane * 2 + 1];
    float a0 = 0.f, a1 = 0.f;
#pragma unroll
    for (int k = 0; k <= HOP; k++) {
        float2 h = *(const float2*)(g_H + (size_t)k * N_NODES * N_OUT +
                                    (size_t)n * N_OUT + lane * 2);
        float p = fmaf(h.x, s0, h.y * s1);
#pragma unroll
        for (int off = 16; off; off >>= 1)
            p += __shfl_xor_sync(0xffffffffu, p, off);
        float sg = 1.f / (1.f + __expf(-p));
        a0 = fmaf(sg, h.x, a0);
        a1 = fmaf(sg, h.y, a1);
    }
    out[(size_t)n * N_OUT + lane * 2 + 0] = a0;
    out[(size_t)n * N_OUT + lane * 2 + 1] = a1;
}

// ---------------- launch ----------------------------------------------------
extern "C" void kernel_launch(void* const* d_in, const int* in_sizes, int n_in,
                              void* d_out, int out_size) {
    const float* x = (const float*)d_in[0];
    const void* erow = d_in[1];
    const void* ecol = d_in[2];
    const float* evals = (const float*)d_in[3];
    const float* W1 = (const float*)d_in[4];
    const float* b1 = (const float*)d_in[5];
    const float* W2 = (const float*)d_in[6];
    const float* b2 = (const float*)d_in[7];
    const float* s = (const float*)d_in[8];
    float* out = (float*)d_out;

    int N = in_sizes[0] / N_IN;     // 100000
    int E = in_sizes[3];            // 1600000 (edge_vals is float32)

    float *p_h1, *p_H;
    cudaGetSymbolAddress((void**)&p_h1, g_h1);
    cudaGetSymbolAddress((void**)&p_H, g_H);

    // 1) index dtype detect + convert to int32
    detect_idx_kernel<<<1, 256>>>((const int*)erow);
    convert_idx_kernel<<<(E + 255) / 256, 256>>>(erow, ecol, E);

    // 2) MLP
    {
        dim3 grid((N + 63) / 64, N_HID / 64);
        gemm_nt_kernel<true><<<grid, 256>>>(x, W1, b1, p_h1, N, N_HID, N_IN);
    }
    {
        dim3 grid((N + 63) / 64, N_OUT / 64);
        gemm_nt_kernel<false><<<grid, 256>>>(p_h1, W2, b2, p_H, N, N_OUT, N_HID);
    }

    // 3) zero hop buffers 1..HOP, then propagate
    {
        int n4 = HOP * N * N_OUT / 4;
        zero_kernel<<<(n4 + 255) / 256, 256>>>(p_H + (size_t)N * N_OUT, n4);
    }
    {
        int threads = E * 16;
        int grid = (threads + 255) / 256;
        for (int k = 0; k < HOP; k++)
            spmm_kernel<<<grid, 256>>>(evals, k, E);
    }

    // 4) hop attention -> output
    {
        int threads = N * 32;
        attn_kernel<<<(threads + 255) / 256, 256>>>(s, out, N);
    }
    (void)n_in; (void)out_size;
}

// round 14
// speedup vs baseline: 1.8896x; 1.8896x over previous
#include <cuda_runtime.h>
#include <cuda_bf16.h>
#include <math.h>

#define N_NODES 100000
#define N_IN    512
#define N_HID   256
#define N_OUT   64
#define HOP     10
#define MAX_E   1600000

// ---------------- scratch (device globals; no allocation allowed) ----------
__device__ float g_h1[(size_t)N_NODES * N_HID];                 // 102.4 MB
__device__ float g_H[(size_t)(HOP + 1) * N_NODES * N_OUT];      // 281.6 MB
__device__ int   g_row[MAX_E];
__device__ int   g_col[MAX_E];
__device__ int   g_is32;
// CSR scratch
__device__ int   g_cnt[N_NODES];
__device__ int   g_rowptr[N_NODES + 1];
__device__ int   g_cursor[N_NODES];
__device__ int   g_ccol[MAX_E];
__device__ float g_cval[MAX_E];

// ---------------- index dtype detection ------------------------------------
__global__ void detect_idx_kernel(const int* __restrict__ p) {
    __shared__ int any;
    if (threadIdx.x == 0) any = 0;
    __syncthreads();
    for (int i = threadIdx.x; i < 2048; i += blockDim.x) {
        if (p[2 * i + 1] != 0) any = 1;  // racy OR-write, fine
    }
    __syncthreads();
    if (threadIdx.x == 0) g_is32 = any;
}

__global__ void zero_cnt_kernel(int N) {
    int i = blockIdx.x * blockDim.x + threadIdx.x;
    if (i < N) g_cnt[i] = 0;
}

// convert to int32 AND histogram rows
__global__ void convert_idx_kernel(const void* __restrict__ rp,
                                   const void* __restrict__ cp, int E) {
    int e = blockIdx.x * blockDim.x + threadIdx.x;
    if (e >= E) return;
    int r, c;
    if (g_is32) {
        r = ((const int*)rp)[e];
        c = ((const int*)cp)[e];
    } else {
        r = (int)((const long long*)rp)[e];
        c = (int)((const long long*)cp)[e];
    }
    g_row[e] = r;
    g_col[e] = c;
    atomicAdd(&g_cnt[r], 1);
}

// single-block exclusive scan over g_cnt -> g_rowptr, g_cursor
__global__ __launch_bounds__(1024) void scan_kernel(int N, int E) {
    __shared__ int part[1024];
    int t = threadIdx.x;
    int CH = (N + 1023) >> 10;           // chunk per thread
    int base = t * CH;
    int lim = min(base + CH, N);
    int sum = 0;
    for (int i = base; i < lim; i++) sum += g_cnt[i];
    part[t] = sum;
    __syncthreads();
    // Hillis-Steele inclusive scan of 1024 partials
    for (int off = 1; off < 1024; off <<= 1) {
        int v = (t >= off) ? part[t - off] : 0;
        __syncthreads();
        part[t] += v;
        __syncthreads();
    }
    int run = part[t] - sum;             // exclusive prefix of this chunk
    for (int i = base; i < lim; i++) {
        g_rowptr[i] = run;
        g_cursor[i] = run;
        run += g_cnt[i];
    }
    if (t == 1023) g_rowptr[N] = E;
}

__global__ void scatter_kernel(const float* __restrict__ vals, int E) {
    int e = blockIdx.x * blockDim.x + threadIdx.x;
    if (e >= E) return;
    int r = g_row[e];
    int j = atomicAdd(&g_cursor[r], 1);
    g_ccol[j] = g_col[e];
    g_cval[j] = vals[e];
}

// ---------------- bf16-split tensor-core NT GEMM ---------------------------
// C[m,n] = act(sum_k A[m,k]*B[n,k] + bias[n]),  A:[M,K] rm, B:[N,K] rm.
// fp32 -> (hi,lo) bf16 split; D += Ah*Bh + Ah*Bl + Al*Bh (Markidis 3-term).

__device__ __forceinline__ void mma16816(float* d, const unsigned* a,
                                         const unsigned* b) {
    asm volatile(
        "mma.sync.aligned.m16n8k16.row.col.f32.bf16.bf16.f32 "
        "{%0,%1,%2,%3}, {%4,%5,%6,%7}, {%8,%9}, {%0,%1,%2,%3};\n"
        : "+f"(d[0]), "+f"(d[1]), "+f"(d[2]), "+f"(d[3])
        : "r"(a[0]), "r"(a[1]), "r"(a[2]), "r"(a[3]), "r"(b[0]), "r"(b[1]));
}

#define GLDS 34  // BK + 2 bf16 pad: 68-byte row stride, conflict-free frags

template <bool RELU>
__global__ __launch_bounds__(256) void gemm_bf16x3_kernel(
    const float* __restrict__ A, const float* __restrict__ B,
    const float* __restrict__ bias, float* __restrict__ C,
    int M, int Ncols, int K) {
    const int BM = 128, BN = 64, BK = 32;
    __shared__ __align__(16) __nv_bfloat16 Ah[BM][GLDS];
    __shared__ __align__(16) __nv_bfloat16 Al[BM][GLDS];
    __shared__ __align__(16) __nv_bfloat16 Bh[BN][GLDS];
    __shared__ __align__(16) __nv_bfloat16 Bl[BN][GLDS];

    int tid = threadIdx.x;
    int warp = tid >> 5, lane = tid & 31;
    int wm = warp & 3, wn = warp >> 2;       // 4 x 2 warp grid
    int grp = lane >> 2, qid = lane & 3;     // mma fragment coords
    int row0 = blockIdx.x * BM, col0 = blockIdx.y * BN;

    float acc[2][4][4];
#pragma unroll
    for (int i = 0; i < 2; i++)
#pragma unroll
        for (int j = 0; j < 4; j++)
#pragma unroll
            for (int r = 0; r < 4; r++) acc[i][j][r] = 0.f;

    int lrow = tid >> 3;       // 0..31
    int lcq = tid & 7;         // float4 group along K

    for (int k0 = 0; k0 < K; k0 += BK) {
#pragma unroll
        for (int p = 0; p < 4; p++) {
            int r = lrow + p * 32;
            float4 f = make_float4(0.f, 0.f, 0.f, 0.f);
            if (row0 + r < M)
                f = *(const float4*)(A + (long long)(row0 + r) * K + k0 + lcq * 4);
            __nv_bfloat16 hx = __float2bfloat16_rn(f.x);
            __nv_bfloat16 hy = __float2bfloat16_rn(f.y);
            __nv_bfloat16 hz = __float2bfloat16_rn(f.z);
            __nv_bfloat16 hw = __float2bfloat16_rn(f.w);
            *(__nv_bfloat162*)&Ah[r][lcq * 4 + 0] = __nv_bfloat162(hx, hy);
            *(__nv_bfloat162*)&Ah[r][lcq * 4 + 2] = __nv_bfloat162(hz, hw);
            *(__nv_bfloat162*)&Al[r][lcq * 4 + 0] = __nv_bfloat162(
                __float2bfloat16_rn(f.x - __bfloat162float(hx)),
                __float2bfloat16_rn(f.y - __bfloat162float(hy)));
            *(__nv_bfloat162*)&Al[r][lcq * 4 + 2] = __nv_bfloat162(
                __float2bfloat16_rn(f.z - __bfloat162float(hz)),
                __float2bfloat16_rn(f.w - __bfloat162float(hw)));
        }
#pragma unroll
        for (int p = 0; p < 2; p++) {
            int r = lrow + p * 32;
            float4 f = *(const float4*)(B + (long long)(col0 + r) * K + k0 + lcq * 4);
            __nv_bfloat16 hx = __float2bfloat16_rn(f.x);
            __nv_bfloat16 hy = __float2bfloat16_rn(f.y);
            __nv_bfloat16 hz = __float2bfloat16_rn(f.z);
            __nv_bfloat16 hw = __float2bfloat16_rn(f.w);
            *(__nv_bfloat162*)&Bh[r][lcq * 4 + 0] = __nv_bfloat162(hx, hy);
            *(__nv_bfloat162*)&Bh[r][lcq * 4 + 2] = __nv_bfloat162(hz, hw);
            *(__nv_bfloat162*)&Bl[r][lcq * 4 + 0] = __nv_bfloat162(
                __float2bfloat16_rn(f.x - __bfloat162float(hx)),
                __float2bfloat16_rn(f.y - __bfloat162float(hy)));
            *(__nv_bfloat162*)&Bl[r][lcq * 4 + 2] = __nv_bfloat162(
                __float2bfloat16_rn(f.z - __bfloat162float(hz)),
                __float2bfloat16_rn(f.w - __bfloat162float(hw)));
        }
        __syncthreads();

#pragma unroll
        for (int ks = 0; ks < BK; ks += 16) {
            unsigned afh[2][4], afl[2][4];
#pragma unroll
            for (int i = 0; i < 2; i++) {
                int rb = wm * 32 + i * 16;
#pragma unroll
                for (int r = 0; r < 4; r++) {
                    int rr = rb + grp + (r & 1) * 8;
                    int cc = ks + qid * 2 + (r >> 1) * 8;
                    afh[i][r] = *(const unsigned*)&Ah[rr][cc];
                    afl[i][r] = *(const unsigned*)&Al[rr][cc];
                }
            }
#pragma unroll
            for (int j = 0; j < 4; j++) {
                int nb = wn * 32 + j * 8;
                unsigned bfh[2], bfl[2];
                bfh[0] = *(const unsigned*)&Bh[nb + grp][ks + qid * 2];
                bfh[1] = *(const unsigned*)&Bh[nb + grp][ks + qid * 2 + 8];
                bfl[0] = *(const unsigned*)&Bl[nb + grp][ks + qid * 2];
                bfl[1] = *(const unsigned*)&Bl[nb + grp][ks + qid * 2 + 8];
#pragma unroll
                for (int i = 0; i < 2; i++) {
                    mma16816(acc[i][j], afh[i], bfh);
                    mma16816(acc[i][j], afh[i], bfl);
                    mma16816(acc[i][j], afl[i], bfh);
                }
            }
        }
        __syncthreads();
    }

#pragma unroll
    for (int i = 0; i < 2; i++) {
#pragma unroll
        for (int j = 0; j < 4; j++) {
            int col = col0 + wn * 32 + j * 8 + qid * 2;
            float bz0 = bias[col], bz1 = bias[col + 1];
            int r0 = row0 + wm * 32 + i * 16 + grp;
#pragma unroll
            for (int h = 0; h < 2; h++) {
                int m = r0 + h * 8;
                if (m >= M) continue;
                float v0 = acc[i][j][h * 2 + 0] + bz0;
                float v1 = acc[i][j][h * 2 + 1] + bz1;
                if (RELU) { v0 = fmaxf(v0, 0.f); v1 = fmaxf(v1, 0.f); }
                *(float2*)(C + (long long)m * Ncols + col) = make_float2(v0, v1);
            }
        }
    }
}

// ---------------- CSR SpMM (row-parallel, atomic-free) ---------------------
// 16 lanes per row; lane l accumulates float4 [l*4, l*4+4) over row's edges.
__global__ void spmm_csr_kernel(int hop, int N) {
    int g = blockIdx.x * blockDim.x + threadIdx.x;
    int row = g >> 4;
    int l = g & 15;
    if (row >= N) return;
    const float* hin = g_H + (size_t)hop * N_NODES * N_OUT;
    float* hout = g_H + (size_t)(hop + 1) * N_NODES * N_OUT;
    int j = g_rowptr[row], end = g_rowptr[row + 1];
    float4 acc = make_float4(0.f, 0.f, 0.f, 0.f);
    for (; j < end; j++) {
        int c = g_ccol[j];
        float v = g_cval[j];
        float4 h = *(const float4*)(hin + (size_t)c * N_OUT + l * 4);
        acc.x = fmaf(v, h.x, acc.x);
        acc.y = fmaf(v, h.y, acc.y);
        acc.z = fmaf(v, h.z, acc.z);
        acc.w = fmaf(v, h.w, acc.w);
    }
    *(float4*)(hout + (size_t)row * N_OUT + l * 4) = acc;
}

// ---------------- hop attention --------------------------------------------
__global__ void attn_kernel(const float* __restrict__ s,
                            float* __restrict__ out, int N) {
    int g = blockIdx.x * blockDim.x + threadIdx.x;
    int n = g >> 5;
    int lane = g & 31;
    if (n >= N) return;
    float s0 = s[lane * 2 + 0];
    float s1 = s[lane * 2 + 1];
    float a0 = 0.f, a1 = 0.f;
#pragma unroll
    for (int k = 0; k <= HOP; k++) {
        float2 h = *(const float2*)(g_H + (size_t)k * N_NODES * N_OUT +
                                    (size_t)n * N_OUT + lane * 2);
        float p = fmaf(h.x, s0, h.y * s1);
#pragma unroll
        for (int off = 16; off; off >>= 1)
            p += __shfl_xor_sync(0xffffffffu, p, off);
        float sg = 1.f / (1.f + __expf(-p));
        a0 = fmaf(sg, h.x, a0);
        a1 = fmaf(sg, h.y, a1);
    }
    out[(size_t)n * N_OUT + lane * 2 + 0] = a0;
    out[(size_t)n * N_OUT + lane * 2 + 1] = a1;
}

// ---------------- launch ----------------------------------------------------
extern "C" void kernel_launch(void* const* d_in, const int* in_sizes, int n_in,
                              void* d_out, int out_size) {
    const float* x = (const float*)d_in[0];
    const void* erow = d_in[1];
    const void* ecol = d_in[2];
    const float* evals = (const float*)d_in[3];
    const float* W1 = (const float*)d_in[4];
    const float* b1 = (const float*)d_in[5];
    const float* W2 = (const float*)d_in[6];
    const float* b2 = (const float*)d_in[7];
    const float* s = (const float*)d_in[8];
    float* out = (float*)d_out;

    int N = in_sizes[0] / N_IN;     // 100000
    int E = in_sizes[3];            // 1600000 (edge_vals is float32)

    float *p_h1, *p_H;
    cudaGetSymbolAddress((void**)&p_h1, g_h1);
    cudaGetSymbolAddress((void**)&p_H, g_H);

    // 1) CSR build: detect dtype, zero counts, convert+histogram, scan, scatter
    detect_idx_kernel<<<1, 256>>>((const int*)erow);
    zero_cnt_kernel<<<(N + 255) / 256, 256>>>(N);
    convert_idx_kernel<<<(E + 255) / 256, 256>>>(erow, ecol, E);
    scan_kernel<<<1, 1024>>>(N, E);
    scatter_kernel<<<(E + 255) / 256, 256>>>(evals, E);

    // 2) MLP (bf16-split tensor-core GEMMs)
    {
        dim3 grid((N + 127) / 128, N_HID / 64);
        gemm_bf16x3_kernel<true><<<grid, 256>>>(x, W1, b1, p_h1, N, N_HID, N_IN);
    }
    {
        dim3 grid((N + 127) / 128, N_OUT / 64);
        gemm_bf16x3_kernel<false><<<grid, 256>>>(p_h1, W2, b2, p_H, N, N_OUT, N_HID);
    }

    // 3) multi-hop propagation (CSR, atomic-free)
    {
        int threads = N * 16;
        int grid = (threads + 255) / 256;
        for (int k = 0; k < HOP; k++)
            spmm_csr_kernel<<<grid, 256>>>(k, N);
    }

    // 4) hop attention -> output
    {
        int threads = N * 32;
        attn_kernel<<<(threads + 255) / 256, 256>>>(s, out, N);
    }
    (void)n_in; (void)out_size;
}

// round 15
// speedup vs baseline: 2.1804x; 1.1539x over previous
#include <cuda_runtime.h>
#include <cuda_bf16.h>
#include <math.h>

#define N_NODES 100000
#define N_IN    512
#define N_HID   256
#define N_OUT   64
#define HOP     10
#define MAX_E   1600000

// ---------------- scratch (device globals; no allocation allowed) ----------
__device__ float g_h1[(size_t)N_NODES * N_HID];                 // 102.4 MB
__device__ float g_H[(size_t)(HOP + 1) * N_NODES * N_OUT];      // 281.6 MB
__device__ int   g_row[MAX_E];
__device__ int   g_col[MAX_E];
__device__ int   g_is32;
// CSR scratch
__device__ int   g_cnt[N_NODES];
__device__ int   g_rowstart[N_NODES];
__device__ int   g_cursor[N_NODES];
__device__ int   g_alloc;
__device__ int   g_ccol[MAX_E];
__device__ float g_cval[MAX_E];

// ---------------- index dtype detection ------------------------------------
__global__ void detect_idx_kernel(const int* __restrict__ p) {
    __shared__ int any;
    if (threadIdx.x == 0) any = 0;
    __syncthreads();
    for (int i = threadIdx.x; i < 2048; i += blockDim.x) {
        if (p[2 * i + 1] != 0) any = 1;  // racy OR-write, fine
    }
    __syncthreads();
    if (threadIdx.x == 0) g_is32 = any;
}

__global__ void zero_cnt_kernel(int N) {
    int i = blockIdx.x * blockDim.x + threadIdx.x;
    if (i < N) g_cnt[i] = 0;
    if (i == 0) g_alloc = 0;
}

// convert to int32 AND histogram rows
__global__ void convert_idx_kernel(const void* __restrict__ rp,
                                   const void* __restrict__ cp, int E) {
    int e = blockIdx.x * blockDim.x + threadIdx.x;
    if (e >= E) return;
    int r, c;
    if (g_is32) {
        r = ((const int*)rp)[e];
        c = ((const int*)cp)[e];
    } else {
        r = (int)((const long long*)rp)[e];
        c = (int)((const long long*)cp)[e];
    }
    g_row[e] = r;
    g_col[e] = c;
    atomicAdd(&g_cnt[r], 1);
}

// parallel segment allocation: each row gets a contiguous [start, start+cnt)
// slice of the edge arrays; segment order across rows is irrelevant for CSR.
__global__ void alloc_kernel(int N) {
    int i = blockIdx.x * blockDim.x + threadIdx.x;
    if (i >= N) return;
    int c = g_cnt[i];
    int s = atomicAdd(&g_alloc, c);
    g_rowstart[i] = s;
    g_cursor[i] = s;
}

__global__ void scatter_kernel(const float* __restrict__ vals, int E) {
    int e = blockIdx.x * blockDim.x + threadIdx.x;
    if (e >= E) return;
    int r = g_row[e];
    int j = atomicAdd(&g_cursor[r], 1);
    g_ccol[j] = g_col[e];
    g_cval[j] = vals[e];
}

// ---------------- bf16-split tensor-core NT GEMM ---------------------------
// C[m,n] = act(sum_k A[m,k]*B[n,k] + bias[n]),  A:[M,K] rm, B:[N,K] rm.
// fp32 -> (hi,lo) bf16 split; D += Ah*Bh + Ah*Bl + Al*Bh (Markidis 3-term).

__device__ __forceinline__ void mma16816(float* d, const unsigned* a,
                                         const unsigned* b) {
    asm volatile(
        "mma.sync.aligned.m16n8k16.row.col.f32.bf16.bf16.f32 "
        "{%0,%1,%2,%3}, {%4,%5,%6,%7}, {%8,%9}, {%0,%1,%2,%3};\n"
        : "+f"(d[0]), "+f"(d[1]), "+f"(d[2]), "+f"(d[3])
        : "r"(a[0]), "r"(a[1]), "r"(a[2]), "r"(a[3]), "r"(b[0]), "r"(b[1]));
}

#define GLDS 34  // BK + 2 bf16 pad: 68-byte row stride, conflict-free frags

template <bool RELU>
__global__ __launch_bounds__(256) void gemm_bf16x3_kernel(
    const float* __restrict__ A, const float* __restrict__ B,
    const float* __restrict__ bias, float* __restrict__ C,
    int M, int Ncols, int K) {
    const int BM = 128, BN = 64, BK = 32;
    __shared__ __align__(16) __nv_bfloat16 Ah[BM][GLDS];
    __shared__ __align__(16) __nv_bfloat16 Al[BM][GLDS];
    __shared__ __align__(16) __nv_bfloat16 Bh[BN][GLDS];
    __shared__ __align__(16) __nv_bfloat16 Bl[BN][GLDS];

    int tid = threadIdx.x;
    int warp = tid >> 5, lane = tid & 31;
    int wm = warp & 3, wn = warp >> 2;       // 4 x 2 warp grid
    int grp = lane >> 2, qid = lane & 3;     // mma fragment coords
    int row0 = blockIdx.x * BM, col0 = blockIdx.y * BN;

    float acc[2][4][4];
#pragma unroll
    for (int i = 0; i < 2; i++)
#pragma unroll
        for (int j = 0; j < 4; j++)
#pragma unroll
            for (int r = 0; r < 4; r++) acc[i][j][r] = 0.f;

    int lrow = tid >> 3;       // 0..31
    int lcq = tid & 7;         // float4 group along K

    for (int k0 = 0; k0 < K; k0 += BK) {
#pragma unroll
        for (int p = 0; p < 4; p++) {
            int r = lrow + p * 32;
            float4 f = make_float4(0.f, 0.f, 0.f, 0.f);
            if (row0 + r < M)
                f = *(const float4*)(A + (long long)(row0 + r) * K + k0 + lcq * 4);
            __nv_bfloat16 hx = __float2bfloat16_rn(f.x);
            __nv_bfloat16 hy = __float2bfloat16_rn(f.y);
            __nv_bfloat16 hz = __float2bfloat16_rn(f.z);
            __nv_bfloat16 hw = __float2bfloat16_rn(f.w);
            *(__nv_bfloat162*)&Ah[r][lcq * 4 + 0] = __nv_bfloat162(hx, hy);
            *(__nv_bfloat162*)&Ah[r][lcq * 4 + 2] = __nv_bfloat162(hz, hw);
            *(__nv_bfloat162*)&Al[r][lcq * 4 + 0] = __nv_bfloat162(
                __float2bfloat16_rn(f.x - __bfloat162float(hx)),
                __float2bfloat16_rn(f.y - __bfloat162float(hy)));
            *(__nv_bfloat162*)&Al[r][lcq * 4 + 2] = __nv_bfloat162(
                __float2bfloat16_rn(f.z - __bfloat162float(hz)),
                __float2bfloat16_rn(f.w - __bfloat162float(hw)));
        }
#pragma unroll
        for (int p = 0; p < 2; p++) {
            int r = lrow + p * 32;
            float4 f = *(const float4*)(B + (long long)(col0 + r) * K + k0 + lcq * 4);
            __nv_bfloat16 hx = __float2bfloat16_rn(f.x);
            __nv_bfloat16 hy = __float2bfloat16_rn(f.y);
            __nv_bfloat16 hz = __float2bfloat16_rn(f.z);
            __nv_bfloat16 hw = __float2bfloat16_rn(f.w);
            *(__nv_bfloat162*)&Bh[r][lcq * 4 + 0] = __nv_bfloat162(hx, hy);
            *(__nv_bfloat162*)&Bh[r][lcq * 4 + 2] = __nv_bfloat162(hz, hw);
            *(__nv_bfloat162*)&Bl[r][lcq * 4 + 0] = __nv_bfloat162(
                __float2bfloat16_rn(f.x - __bfloat162float(hx)),
                __float2bfloat16_rn(f.y - __bfloat162float(hy)));
            *(__nv_bfloat162*)&Bl[r][lcq * 4 + 2] = __nv_bfloat162(
                __float2bfloat16_rn(f.z - __bfloat162float(hz)),
                __float2bfloat16_rn(f.w - __bfloat162float(hw)));
        }
        __syncthreads();

#pragma unroll
        for (int ks = 0; ks < BK; ks += 16) {
            unsigned afh[2][4], afl[2][4];
#pragma unroll
            for (int i = 0; i < 2; i++) {
                int rb = wm * 32 + i * 16;
#pragma unroll
                for (int r = 0; r < 4; r++) {
                    int rr = rb + grp + (r & 1) * 8;
                    int cc = ks + qid * 2 + (r >> 1) * 8;
                    afh[i][r] = *(const unsigned*)&Ah[rr][cc];
                    afl[i][r] = *(const unsigned*)&Al[rr][cc];
                }
            }
#pragma unroll
            for (int j = 0; j < 4; j++) {
                int nb = wn * 32 + j * 8;
                unsigned bfh[2], bfl[2];
                bfh[0] = *(const unsigned*)&Bh[nb + grp][ks + qid * 2];
                bfh[1] = *(const unsigned*)&Bh[nb + grp][ks + qid * 2 + 8];
                bfl[0] = *(const unsigned*)&Bl[nb + grp][ks + qid * 2];
                bfl[1] = *(const unsigned*)&Bl[nb + grp][ks + qid * 2 + 8];
#pragma unroll
                for (int i = 0; i < 2; i++) {
                    mma16816(acc[i][j], afh[i], bfh);
                    mma16816(acc[i][j], afh[i], bfl);
                    mma16816(acc[i][j], afl[i], bfh);
                }
            }
        }
        __syncthreads();
    }

#pragma unroll
    for (int i = 0; i < 2; i++) {
#pragma unroll
        for (int j = 0; j < 4; j++) {
            int col = col0 + wn * 32 + j * 8 + qid * 2;
            float bz0 = bias[col], bz1 = bias[col + 1];
            int r0 = row0 + wm * 32 + i * 16 + grp;
#pragma unroll
            for (int h = 0; h < 2; h++) {
                int m = r0 + h * 8;
                if (m >= M) continue;
                float v0 = acc[i][j][h * 2 + 0] + bz0;
                float v1 = acc[i][j][h * 2 + 1] + bz1;
                if (RELU) { v0 = fmaxf(v0, 0.f); v1 = fmaxf(v1, 0.f); }
                *(float2*)(C + (long long)m * Ncols + col) = make_float2(v0, v1);
            }
        }
    }
}

// ---------------- CSR SpMM (row-parallel, atomic-free) ---------------------
// 16 lanes per row; lane l accumulates float4 [l*4, l*4+4) over row's edges.
__global__ void spmm_csr_kernel(int hop, int N) {
    int g = blockIdx.x * blockDim.x + threadIdx.x;
    int row = g >> 4;
    int l = g & 15;
    if (row >= N) return;
    const float* hin = g_H + (size_t)hop * N_NODES * N_OUT;
    float* hout = g_H + (size_t)(hop + 1) * N_NODES * N_OUT;
    int j = g_rowstart[row];
    int end = j + g_cnt[row];
    float4 acc = make_float4(0.f, 0.f, 0.f, 0.f);
    for (; j < end; j++) {
        int c = g_ccol[j];
        float v = g_cval[j];
        float4 h = *(const float4*)(hin + (size_t)c * N_OUT + l * 4);
        acc.x = fmaf(v, h.x, acc.x);
        acc.y = fmaf(v, h.y, acc.y);
        acc.z = fmaf(v, h.z, acc.z);
        acc.w = fmaf(v, h.w, acc.w);
    }
    *(float4*)(hout + (size_t)row * N_OUT + l * 4) = acc;
}

// ---------------- hop attention --------------------------------------------
__global__ void attn_kernel(const float* __restrict__ s,
                            float* __restrict__ out, int N) {
    int g = blockIdx.x * blockDim.x + threadIdx.x;
    int n = g >> 5;
    int lane = g & 31;
    if (n >= N) return;
    float s0 = s[lane * 2 + 0];
    float s1 = s[lane * 2 + 1];
    float a0 = 0.f, a1 = 0.f;
#pragma unroll
    for (int k = 0; k <= HOP; k++) {
        float2 h = *(const float2*)(g_H + (size_t)k * N_NODES * N_OUT +
                                    (size_t)n * N_OUT + lane * 2);
        float p = fmaf(h.x, s0, h.y * s1);
#pragma unroll
        for (int off = 16; off; off >>= 1)
            p += __shfl_xor_sync(0xffffffffu, p, off);
        float sg = 1.f / (1.f + __expf(-p));
        a0 = fmaf(sg, h.x, a0);
        a1 = fmaf(sg, h.y, a1);
    }
    out[(size_t)n * N_OUT + lane * 2 + 0] = a0;
    out[(size_t)n * N_OUT + lane * 2 + 1] = a1;
}

// ---------------- launch ----------------------------------------------------
extern "C" void kernel_launch(void* const* d_in, const int* in_sizes, int n_in,
                              void* d_out, int out_size) {
    const float* x = (const float*)d_in[0];
    const void* erow = d_in[1];
    const void* ecol = d_in[2];
    const float* evals = (const float*)d_in[3];
    const float* W1 = (const float*)d_in[4];
    const float* b1 = (const float*)d_in[5];
    const float* W2 = (const float*)d_in[6];
    const float* b2 = (const float*)d_in[7];
    const float* s = (const float*)d_in[8];
    float* out = (float*)d_out;

    int N = in_sizes[0] / N_IN;     // 100000
    int E = in_sizes[3];            // 1600000 (edge_vals is float32)

    float *p_h1, *p_H;
    cudaGetSymbolAddress((void**)&p_h1, g_h1);
    cudaGetSymbolAddress((void**)&p_H, g_H);

    // 1) CSR build: detect dtype, zero counts, convert+histogram,
    //    parallel segment alloc (replaces single-block scan), scatter
    detect_idx_kernel<<<1, 256>>>((const int*)erow);
    zero_cnt_kernel<<<(N + 255) / 256, 256>>>(N);
    convert_idx_kernel<<<(E + 255) / 256, 256>>>(erow, ecol, E);
    alloc_kernel<<<(N + 255) / 256, 256>>>(N);
    scatter_kernel<<<(E + 255) / 256, 256>>>(evals, E);

    // 2) MLP (bf16-split tensor-core GEMMs)
    {
        dim3 grid((N + 127) / 128, N_HID / 64);
        gemm_bf16x3_kernel<true><<<grid, 256>>>(x, W1, b1, p_h1, N, N_HID, N_IN);
    }
    {
        dim3 grid((N + 127) / 128, N_OUT / 64);
        gemm_bf16x3_kernel<false><<<grid, 256>>>(p_h1, W2, b2, p_H, N, N_OUT, N_HID);
    }

    // 3) multi-hop propagation (CSR, atomic-free)
    {
        int threads = N * 16;
        int grid = (threads + 255) / 256;
        for (int k = 0; k < HOP; k++)
            spmm_csr_kernel<<<grid, 256>>>(k, N);
    }

    // 4) hop attention -> output
    {
        int threads = N * 32;
        attn_kernel<<<(threads + 255) / 256, 256>>>(s, out, N);
    }
    (void)n_in; (void)out_size;
}

// round 16
// speedup vs baseline: 2.2057x; 1.0116x over previous
#include <cuda_runtime.h>
#include <cuda_bf16.h>
#include <math.h>

#define N_NODES 100000
#define N_IN    512
#define N_HID   256
#define N_OUT   64
#define HOP     10
#define MAX_E   1600000

// ---------------- scratch (device globals; no allocation allowed) ----------
__device__ float g_h1[(size_t)N_NODES * N_HID];                 // 102.4 MB
__device__ float g_H[(size_t)(HOP + 1) * N_NODES * N_OUT];      // 281.6 MB
__device__ int   g_row[MAX_E];
__device__ int   g_col[MAX_E];
__device__ int   g_is32;
// CSR scratch
__device__ int   g_cnt[N_NODES];
__device__ int   g_rowstart[N_NODES];
__device__ int   g_cursor[N_NODES];
__device__ int   g_alloc;
__device__ int   g_ccol[MAX_E];
__device__ float g_cval[MAX_E];

// ---------------- index dtype detection ------------------------------------
__global__ void detect_idx_kernel(const int* __restrict__ p) {
    __shared__ int any;
    if (threadIdx.x == 0) any = 0;
    __syncthreads();
    for (int i = threadIdx.x; i < 2048; i += blockDim.x) {
        if (p[2 * i + 1] != 0) any = 1;  // racy OR-write, fine
    }
    __syncthreads();
    if (threadIdx.x == 0) g_is32 = any;
}

__global__ void zero_cnt_kernel(int N) {
    int i = blockIdx.x * blockDim.x + threadIdx.x;
    if (i < N) g_cnt[i] = 0;
    if (i == 0) g_alloc = 0;
}

// convert to int32 AND histogram rows
__global__ void convert_idx_kernel(const void* __restrict__ rp,
                                   const void* __restrict__ cp, int E) {
    int e = blockIdx.x * blockDim.x + threadIdx.x;
    if (e >= E) return;
    int r, c;
    if (g_is32) {
        r = ((const int*)rp)[e];
        c = ((const int*)cp)[e];
    } else {
        r = (int)((const long long*)rp)[e];
        c = (int)((const long long*)cp)[e];
    }
    g_row[e] = r;
    g_col[e] = c;
    atomicAdd(&g_cnt[r], 1);
}

// parallel segment allocation: each row gets a contiguous [start, start+cnt)
// slice of the edge arrays; segment order across rows is irrelevant for CSR.
__global__ void alloc_kernel(int N) {
    int i = blockIdx.x * blockDim.x + threadIdx.x;
    if (i >= N) return;
    int c = g_cnt[i];
    int s = atomicAdd(&g_alloc, c);
    g_rowstart[i] = s;
    g_cursor[i] = s;
}

__global__ void scatter_kernel(const float* __restrict__ vals, int E) {
    int e = blockIdx.x * blockDim.x + threadIdx.x;
    if (e >= E) return;
    int r = g_row[e];
    int j = atomicAdd(&g_cursor[r], 1);
    g_ccol[j] = g_col[e];
    g_cval[j] = vals[e];
}

// ---------------- bf16-split tensor-core NT GEMM ---------------------------
// C[m,n] = act(sum_k A[m,k]*B[n,k] + bias[n]),  A:[M,K] rm, B:[N,K] rm.
// fp32 -> (hi,lo) bf16 split; D += Ah*Bh + Ah*Bl + Al*Bh (Markidis 3-term).

__device__ __forceinline__ void mma16816(float* d, const unsigned* a,
                                         const unsigned* b) {
    asm volatile(
        "mma.sync.aligned.m16n8k16.row.col.f32.bf16.bf16.f32 "
        "{%0,%1,%2,%3}, {%4,%5,%6,%7}, {%8,%9}, {%0,%1,%2,%3};\n"
        : "+f"(d[0]), "+f"(d[1]), "+f"(d[2]), "+f"(d[3])
        : "r"(a[0]), "r"(a[1]), "r"(a[2]), "r"(a[3]), "r"(b[0]), "r"(b[1]));
}

#define GLDS 34  // BK + 2 bf16 pad: 68-byte row stride, conflict-free frags

template <bool RELU>
__global__ __launch_bounds__(256) void gemm_bf16x3_kernel(
    const float* __restrict__ A, const float* __restrict__ B,
    const float* __restrict__ bias, float* __restrict__ C,
    int M, int Ncols, int K) {
    const int BM = 128, BN = 64, BK = 32;
    __shared__ __align__(16) __nv_bfloat16 Ah[BM][GLDS];
    __shared__ __align__(16) __nv_bfloat16 Al[BM][GLDS];
    __shared__ __align__(16) __nv_bfloat16 Bh[BN][GLDS];
    __shared__ __align__(16) __nv_bfloat16 Bl[BN][GLDS];

    int tid = threadIdx.x;
    int warp = tid >> 5, lane = tid & 31;
    int wm = warp & 3, wn = warp >> 2;       // 4 x 2 warp grid
    int grp = lane >> 2, qid = lane & 3;     // mma fragment coords
    int row0 = blockIdx.x * BM, col0 = blockIdx.y * BN;

    float acc[2][4][4];
#pragma unroll
    for (int i = 0; i < 2; i++)
#pragma unroll
        for (int j = 0; j < 4; j++)
#pragma unroll
            for (int r = 0; r < 4; r++) acc[i][j][r] = 0.f;

    int lrow = tid >> 3;       // 0..31
    int lcq = tid & 7;         // float4 group along K

    for (int k0 = 0; k0 < K; k0 += BK) {
#pragma unroll
        for (int p = 0; p < 4; p++) {
            int r = lrow + p * 32;
            float4 f = make_float4(0.f, 0.f, 0.f, 0.f);
            if (row0 + r < M)
                f = *(const float4*)(A + (long long)(row0 + r) * K + k0 + lcq * 4);
            __nv_bfloat16 hx = __float2bfloat16_rn(f.x);
            __nv_bfloat16 hy = __float2bfloat16_rn(f.y);
            __nv_bfloat16 hz = __float2bfloat16_rn(f.z);
            __nv_bfloat16 hw = __float2bfloat16_rn(f.w);
            *(__nv_bfloat162*)&Ah[r][lcq * 4 + 0] = __nv_bfloat162(hx, hy);
            *(__nv_bfloat162*)&Ah[r][lcq * 4 + 2] = __nv_bfloat162(hz, hw);
            *(__nv_bfloat162*)&Al[r][lcq * 4 + 0] = __nv_bfloat162(
                __float2bfloat16_rn(f.x - __bfloat162float(hx)),
                __float2bfloat16_rn(f.y - __bfloat162float(hy)));
            *(__nv_bfloat162*)&Al[r][lcq * 4 + 2] = __nv_bfloat162(
                __float2bfloat16_rn(f.z - __bfloat162float(hz)),
                __float2bfloat16_rn(f.w - __bfloat162float(hw)));
        }
#pragma unroll
        for (int p = 0; p < 2; p++) {
            int r = lrow + p * 32;
            float4 f = *(const float4*)(B + (long long)(col0 + r) * K + k0 + lcq * 4);
            __nv_bfloat16 hx = __float2bfloat16_rn(f.x);
            __nv_bfloat16 hy = __float2bfloat16_rn(f.y);
            __nv_bfloat16 hz = __float2bfloat16_rn(f.z);
            __nv_bfloat16 hw = __float2bfloat16_rn(f.w);
            *(__nv_bfloat162*)&Bh[r][lcq * 4 + 0] = __nv_bfloat162(hx, hy);
            *(__nv_bfloat162*)&Bh[r][lcq * 4 + 2] = __nv_bfloat162(hz, hw);
            *(__nv_bfloat162*)&Bl[r][lcq * 4 + 0] = __nv_bfloat162(
                __float2bfloat16_rn(f.x - __bfloat162float(hx)),
                __float2bfloat16_rn(f.y - __bfloat162float(hy)));
            *(__nv_bfloat162*)&Bl[r][lcq * 4 + 2] = __nv_bfloat162(
                __float2bfloat16_rn(f.z - __bfloat162float(hz)),
                __float2bfloat16_rn(f.w - __bfloat162float(hw)));
        }
        __syncthreads();

#pragma unroll
        for (int ks = 0; ks < BK; ks += 16) {
            unsigned afh[2][4], afl[2][4];
#pragma unroll
            for (int i = 0; i < 2; i++) {
                int rb = wm * 32 + i * 16;
#pragma unroll
                for (int r = 0; r < 4; r++) {
                    int rr = rb + grp + (r & 1) * 8;
                    int cc = ks + qid * 2 + (r >> 1) * 8;
                    afh[i][r] = *(const unsigned*)&Ah[rr][cc];
                    afl[i][r] = *(const unsigned*)&Al[rr][cc];
                }
            }
#pragma unroll
            for (int j = 0; j < 4; j++) {
                int nb = wn * 32 + j * 8;
                unsigned bfh[2], bfl[2];
                bfh[0] = *(const unsigned*)&Bh[nb + grp][ks + qid * 2];
                bfh[1] = *(const unsigned*)&Bh[nb + grp][ks + qid * 2 + 8];
                bfl[0] = *(const unsigned*)&Bl[nb + grp][ks + qid * 2];
                bfl[1] = *(const unsigned*)&Bl[nb + grp][ks + qid * 2 + 8];
#pragma unroll
                for (int i = 0; i < 2; i++) {
                    mma16816(acc[i][j], afh[i], bfh);
                    mma16816(acc[i][j], afh[i], bfl);
                    mma16816(acc[i][j], afl[i], bfh);
                }
            }
        }
        __syncthreads();
    }

#pragma unroll
    for (int i = 0; i < 2; i++) {
#pragma unroll
        for (int j = 0; j < 4; j++) {
            int col = col0 + wn * 32 + j * 8 + qid * 2;
            float bz0 = bias[col], bz1 = bias[col + 1];
            int r0 = row0 + wm * 32 + i * 16 + grp;
#pragma unroll
            for (int h = 0; h < 2; h++) {
                int m = r0 + h * 8;
                if (m >= M) continue;
                float v0 = acc[i][j][h * 2 + 0] + bz0;
                float v1 = acc[i][j][h * 2 + 1] + bz1;
                if (RELU) { v0 = fmaxf(v0, 0.f); v1 = fmaxf(v1, 0.f); }
                *(float2*)(C + (long long)m * Ncols + col) = make_float2(v0, v1);
            }
        }
    }
}

// ---------------- CSR SpMM (warp-per-row, 4-wide pipelined gathers) --------
// 32 lanes per row; lane l accumulates float2 [l*2, l*2+2). Manual unroll-4
// keeps 4 independent h-gathers in flight (MLP=4 vs serial chain).
__global__ void spmm_csr_kernel(int hop, int N) {
    int g = blockIdx.x * blockDim.x + threadIdx.x;
    int row = g >> 5;
    int l = g & 31;
    if (row >= N) return;
    const float* hin = g_H + (size_t)hop * N_NODES * N_OUT;
    float* hout = g_H + (size_t)(hop + 1) * N_NODES * N_OUT;
    int j = g_rowstart[row];
    int end = j + g_cnt[row];
    float acc0 = 0.f, acc1 = 0.f;
    for (; j + 4 <= end; j += 4) {
        int c0 = g_ccol[j + 0], c1 = g_ccol[j + 1];
        int c2 = g_ccol[j + 2], c3 = g_ccol[j + 3];
        float v0 = g_cval[j + 0], v1 = g_cval[j + 1];
        float v2 = g_cval[j + 2], v3 = g_cval[j + 3];
        float2 h0 = *(const float2*)(hin + (size_t)c0 * N_OUT + l * 2);
        float2 h1 = *(const float2*)(hin + (size_t)c1 * N_OUT + l * 2);
        float2 h2 = *(const float2*)(hin + (size_t)c2 * N_OUT + l * 2);
        float2 h3 = *(const float2*)(hin + (size_t)c3 * N_OUT + l * 2);
        acc0 = fmaf(v0, h0.x, acc0); acc1 = fmaf(v0, h0.y, acc1);
        acc0 = fmaf(v1, h1.x, acc0); acc1 = fmaf(v1, h1.y, acc1);
        acc0 = fmaf(v2, h2.x, acc0); acc1 = fmaf(v2, h2.y, acc1);
        acc0 = fmaf(v3, h3.x, acc0); acc1 = fmaf(v3, h3.y, acc1);
    }
    for (; j < end; j++) {
        int c = g_ccol[j];
        float v = g_cval[j];
        float2 h = *(const float2*)(hin + (size_t)c * N_OUT + l * 2);
        acc0 = fmaf(v, h.x, acc0);
        acc1 = fmaf(v, h.y, acc1);
    }
    *(float2*)(hout + (size_t)row * N_OUT + l * 2) = make_float2(acc0, acc1);
}

// ---------------- hop attention --------------------------------------------
__global__ void attn_kernel(const float* __restrict__ s,
                            float* __restrict__ out, int N) {
    int g = blockIdx.x * blockDim.x + threadIdx.x;
    int n = g >> 5;
    int lane = g & 31;
    if (n >= N) return;
    float s0 = s[lane * 2 + 0];
    float s1 = s[lane * 2 + 1];
    float a0 = 0.f, a1 = 0.f;
#pragma unroll
    for (int k = 0; k <= HOP; k++) {
        float2 h = *(const float2*)(g_H + (size_t)k * N_NODES * N_OUT +
                                    (size_t)n * N_OUT + lane * 2);
        float p = fmaf(h.x, s0, h.y * s1);
#pragma unroll
        for (int off = 16; off; off >>= 1)
            p += __shfl_xor_sync(0xffffffffu, p, off);
        float sg = 1.f / (1.f + __expf(-p));
        a0 = fmaf(sg, h.x, a0);
        a1 = fmaf(sg, h.y, a1);
    }
    out[(size_t)n * N_OUT + lane * 2 + 0] = a0;
    out[(size_t)n * N_OUT + lane * 2 + 1] = a1;
}

// ---------------- launch ----------------------------------------------------
extern "C" void kernel_launch(void* const* d_in, const int* in_sizes, int n_in,
                              void* d_out, int out_size) {
    const float* x = (const float*)d_in[0];
    const void* erow = d_in[1];
    const void* ecol = d_in[2];
    const float* evals = (const float*)d_in[3];
    const float* W1 = (const float*)d_in[4];
    const float* b1 = (const float*)d_in[5];
    const float* W2 = (const float*)d_in[6];
    const float* b2 = (const float*)d_in[7];
    const float* s = (const float*)d_in[8];
    float* out = (float*)d_out;

    int N = in_sizes[0] / N_IN;     // 100000
    int E = in_sizes[3];            // 1600000 (edge_vals is float32)

    float *p_h1, *p_H;
    cudaGetSymbolAddress((void**)&p_h1, g_h1);
    cudaGetSymbolAddress((void**)&p_H, g_H);

    // 1) CSR build: detect dtype, zero counts, convert+histogram,
    //    parallel segment alloc, scatter
    detect_idx_kernel<<<1, 256>>>((const int*)erow);
    zero_cnt_kernel<<<(N + 255) / 256, 256>>>(N);
    convert_idx_kernel<<<(E + 255) / 256, 256>>>(erow, ecol, E);
    alloc_kernel<<<(N + 255) / 256, 256>>>(N);
    scatter_kernel<<<(E + 255) / 256, 256>>>(evals, E);

    // 2) MLP (bf16-split tensor-core GEMMs)
    {
        dim3 grid((N + 127) / 128, N_HID / 64);
        gemm_bf16x3_kernel<true><<<grid, 256>>>(x, W1, b1, p_h1, N, N_HID, N_IN);
    }
    {
        dim3 grid((N + 127) / 128, N_OUT / 64);
        gemm_bf16x3_kernel<false><<<grid, 256>>>(p_h1, W2, b2, p_H, N, N_OUT, N_HID);
    }

    // 3) multi-hop propagation (CSR, atomic-free, warp-per-row)
    {
        long long threads = (long long)N * 32;
        int grid = (int)((threads + 255) / 256);
        for (int k = 0; k < HOP; k++)
            spmm_csr_kernel<<<grid, 256>>>(k, N);
    }

    // 4) hop attention -> output
    {
        int threads = N * 32;
        attn_kernel<<<(threads + 255) / 256, 256>>>(s, out, N);
    }
    (void)n_in; (void)out_size;
}